// round 12
// baseline (speedup 1.0000x reference)
#include <cuda_runtime.h>
#include <cuda_bf16.h>
#include <math.h>

// GLIF recurrence, T=4. Two kernels overlapped via PDL:
//  1) params: 2048 ch x 8 = 16384 threads, ONE sigmoid each -> g_chp table,
//     then __threadfence + cudaTriggerProgrammaticLaunchCompletion.
//  2) main: launched with ProgrammaticStreamSerialization so it starts
//     concurrently; issues its x loads FIRST, then cudaGridDependencySynchronize,
//     then reads g_chp. Params latency hides under the first DRAM round-trip.
//
// x: (B=16, PLANE=2048, L=1024) fp32. out: final spike map, fp32 {0,1}.

#define GLIF_T     4
#define GLIF_PLANE 2048
#define GLIF_L     1024
#define GLIF_B     16

// Per-channel constants, 48B (3 x float4):
// [0] A   [1] omg  [2] negLk [3] negR
// [4] vth [5] s0   [6] s1    [7] s2
// [8] s3  [9..11] pad
struct __align__(16) ChParams {
    float v[12];
};
__device__ ChParams g_chp[GLIF_PLANE];

__global__ void glif_params_kernel(
    const float* __restrict__ alpha,
    const float* __restrict__ beta,
    const float* __restrict__ gamma,
    const float* __restrict__ tau,
    const float* __restrict__ Vth,
    const float* __restrict__ leak,
    const float* __restrict__ reVth,
    const float* __restrict__ conduct)
{
    const int idx = blockIdx.x * blockDim.x + threadIdx.x;
    if (idx < GLIF_PLANE * 8) {
        const int c    = idx >> 3;
        const int pidx = idx & 7;

        const float al = (__ldg(&alpha[c]) > 0.0f) ? 1.0f : 0.0f;  // arch_act(sigmoid)==(p>0)
        const float be = (__ldg(&beta[c])  > 0.0f) ? 1.0f : 0.0f;
        const float ga = (__ldg(&gamma[c]) > 0.0f) ? 1.0f : 0.0f;

        float v;
        if      (pidx == 0) v = __ldg(&tau[c]);
        else if (pidx == 1) v = __ldg(&Vth[c]);
        else if (pidx == 2) v = __ldg(&leak[c]);
        else if (pidx == 3) v = __ldg(&reVth[c]);
        else                v = __ldg(&conduct[(pidx - 4) * GLIF_PLANE + c]);

        const float sig = 1.0f / (1.0f + expf(-v));

        float r;
        int slot;
        if (pidx == 0) {
            r = 1.0f - al * (1.0f - sig);  slot = 0;            // A
            g_chp[c].v[1] = 1.0f - ga;                          // omg
            g_chp[c].v[9] = 0.0f; g_chp[c].v[10] = 0.0f; g_chp[c].v[11] = 0.0f;
        } else if (pidx == 1) {
            r = sig;                       slot = 4;            // vth
        } else if (pidx == 2) {
            r = -((1.0f - al) * sig);      slot = 2;            // negLk
        } else if (pidx == 3) {
            r = -((1.0f - ga) * sig);      slot = 3;            // negR
        } else {
            r = 1.0f - be * (1.0f - sig);  slot = 5 + (pidx - 4);  // s_t
        }
        g_chp[c].v[slot] = r;
    }
    // Release the dependent (main) kernel as early as possible.
    __threadfence();
    cudaTriggerProgrammaticLaunchCompletion();
}

__global__ void __launch_bounds__(256) glif_main_kernel(
    const float* __restrict__ x,
    float* __restrict__ out)
{
    const int c  = blockIdx.x & (GLIF_PLANE - 1);   // channel
    const int bh = blockIdx.x >> 11;                // 0..7 -> batches bh, bh+8

    // 32-bit float4 indexing (max index 8.4M, fits easily)
    const unsigned row4  = GLIF_PLANE * (GLIF_L / 4);           // 524288
    const unsigned base4 = (unsigned)bh * row4
                         + (unsigned)c * (GLIF_L / 4) + threadIdx.x;
    const float4* xp = reinterpret_cast<const float4*>(x) + base4;
    float4*       op = reinterpret_cast<float4*>(out) + base4;

    // Issue both independent loads BEFORE waiting on the params grid.
    const float4 xa = __ldcs(xp);
    const float4 xb = __ldcs(xp + 8 * row4);

    // Wait for glif_params_kernel's writes to g_chp to be visible.
    cudaGridDependencySynchronize();

    const float4* pv = reinterpret_cast<const float4*>(&g_chp[c]);
    const float4 p0 = __ldg(pv);
    const float4 p1 = __ldg(pv + 1);
    const float  s3 = __ldg(&g_chp[c].v[8]);
    const float A = p0.x, omg = p0.y, negLk = p0.z, negR = p0.w;
    const float vth = p1.x, s0 = p1.y;
    const float sv[3] = {p1.z, p1.w, s3};

#pragma unroll
    for (int q = 0; q < 2; ++q) {
        const float4 xq = (q == 0) ? xa : xb;
        float xl[4] = {xq.x, xq.y, xq.z, xq.w};
        float ov[4];
#pragma unroll
        for (int j = 0; j < 4; ++j) {
            const float xj = xl[j];
            // t=0: u=0, o=0 -> u1 = x*s0 - Lk
            float uu = fmaf(xj, s0, negLk);
            bool  o  = (uu > vth);
#pragma unroll
            for (int t = 0; t < 3; ++t) {
                // reference order: ((A*u)*(1-ga*o) - Lk) + x*s - R*o
                const float g = o ? omg : 1.0f;
                float m = (A * uu) * g;
                m = m + negLk;
                m = fmaf(xj, sv[t], m);
                if (o) m = m + negR;
                o = (m > vth);
                uu = m;
            }
            ov[j] = o ? 1.0f : 0.0f;
        }
        float4 res;
        res.x = ov[0]; res.y = ov[1]; res.z = ov[2]; res.w = ov[3];
        __stcs(op + (unsigned)(q * 8) * row4, res);
    }
}

extern "C" void kernel_launch(void* const* d_in, const int* in_sizes, int n_in,
                              void* d_out, int out_size) {
    const float* x       = (const float*)d_in[0];
    const float* alpha   = (const float*)d_in[1];
    const float* beta    = (const float*)d_in[2];
    const float* gamma   = (const float*)d_in[3];
    const float* tau     = (const float*)d_in[4];
    const float* Vth     = (const float*)d_in[5];
    const float* leak    = (const float*)d_in[6];
    const float* reVth   = (const float*)d_in[7];
    const float* conduct = (const float*)d_in[8];
    float* out = (float*)d_out;

    glif_params_kernel<<<(GLIF_PLANE * 8 + 255) / 256, 256>>>(
        alpha, beta, gamma, tau, Vth, leak, reVth, conduct);

    // Main kernel with Programmatic Dependent Launch: may begin while the
    // params kernel is still running; device code gates on
    // cudaGridDependencySynchronize().
    const int n_blk = out_size / (GLIF_L * 2);   // 16384 blocks, 2 batches each
    cudaLaunchConfig_t cfg = {};
    cfg.gridDim  = dim3(n_blk, 1, 1);
    cfg.blockDim = dim3(256, 1, 1);
    cfg.dynamicSmemBytes = 0;
    cfg.stream = 0;
    cudaLaunchAttribute attr[1];
    attr[0].id = cudaLaunchAttributeProgrammaticStreamSerialization;
    attr[0].val.programmaticStreamSerializationAllowed = 1;
    cfg.attrs = attr;
    cfg.numAttrs = 1;
    cudaLaunchKernelEx(&cfg, glif_main_kernel, x, out);
}